// round 8
// baseline (speedup 1.0000x reference)
#include <cuda_runtime.h>
#include <cuda_fp16.h>
#include <cstdint>
#include <math.h>

#define N_ROWS 16384
#define C_ROWS 10000
#define D_DIM  256
#define EPS    1e-6f

#define BM 128
#define BN 256
#define BK 64               // K elements per compute chunk (128B rows)
#define NCHUNK 4            // K=256 / 64
#define STAGES 3
#define STAGE_BYTES 49152   // 16KB A + 32KB B
#define SMEM_TOTAL (STAGES * STAGE_BYTES)
#define NTHREADS 512

// ---------------- device scratch (allocation-free rule) ----------------
__device__ __half g_Xs[(size_t)N_ROWS * D_DIM];   // normalized x, fp16
__device__ __half g_Ps[(size_t)C_ROWS * D_DIM];   // normalized p, fp16

// ---------------- helpers ----------------
__device__ __forceinline__ uint32_t smem_u32(const void* p) {
    uint32_t a;
    asm("{ .reg .u64 t; cvta.to.shared.u64 t, %1; cvt.u32.u64 %0, t; }" : "=r"(a) : "l"(p));
    return a;
}
__device__ __forceinline__ void cp_async16(uint32_t dst, const void* src, uint32_t src_bytes) {
    asm volatile("cp.async.cg.shared.global [%0], [%1], 16, %2;"
                 :: "r"(dst), "l"(src), "r"(src_bytes) : "memory");
}
#define CP_COMMIT() asm volatile("cp.async.commit_group;" ::: "memory")
template <int N>
__device__ __forceinline__ void cp_wait() {
    asm volatile("cp.async.wait_group %0;" :: "n"(N) : "memory");
}
__device__ __forceinline__ uint32_t sw128(uint32_t off) { return off ^ ((off >> 3) & 0x70); }

__device__ __forceinline__ void ldsm_x4(uint32_t* r, uint32_t addr) {
    asm volatile("ldmatrix.sync.aligned.m8n8.x4.shared.b16 {%0,%1,%2,%3}, [%4];"
                 : "=r"(r[0]), "=r"(r[1]), "=r"(r[2]), "=r"(r[3]) : "r"(addr));
}
__device__ __forceinline__ void ldsm_x2(uint32_t* r, uint32_t addr) {
    asm volatile("ldmatrix.sync.aligned.m8n8.x2.shared.b16 {%0,%1}, [%2];"
                 : "=r"(r[0]), "=r"(r[1]) : "r"(addr));
}
__device__ __forceinline__ void mma_fp16(float* d, const uint32_t* a, const uint32_t* b) {
    asm volatile("mma.sync.aligned.m16n8k16.row.col.f32.f16.f16.f32 "
                 "{%0,%1,%2,%3}, {%4,%5,%6,%7}, {%8,%9}, {%0,%1,%2,%3};"
                 : "+f"(d[0]), "+f"(d[1]), "+f"(d[2]), "+f"(d[3])
                 : "r"(a[0]), "r"(a[1]), "r"(a[2]), "r"(a[3]), "r"(b[0]), "r"(b[1]));
}

// ---------------- normalize + fp16 convert, warp per row ----------------
__global__ void normalize_fp16_kernel(const float* __restrict__ src,
                                      __half* __restrict__ dst, int rows) {
    int warp = (blockIdx.x * blockDim.x + threadIdx.x) >> 5;
    int lane = threadIdx.x & 31;
    if (warp >= rows) return;
    const float4* p = reinterpret_cast<const float4*>(src + (size_t)warp * D_DIM);
    float4 v0 = p[lane];
    float4 v1 = p[lane + 32];
    float sum = v0.x * v0.x + v0.y * v0.y + v0.z * v0.z + v0.w * v0.w
              + v1.x * v1.x + v1.y * v1.y + v1.z * v1.z + v1.w * v1.w;
#pragma unroll
    for (int o = 16; o > 0; o >>= 1) sum += __shfl_xor_sync(0xffffffffu, sum, o);
    const float inv = 1.0f / fmaxf(sqrtf(sum), EPS);

    __half* row = dst + (size_t)warp * D_DIM;
    __half2 a, b;
    a.x = __float2half_rn(v0.x * inv); a.y = __float2half_rn(v0.y * inv);
    b.x = __float2half_rn(v0.z * inv); b.y = __float2half_rn(v0.w * inv);
    *reinterpret_cast<__half2*>(row + lane * 4) = a;
    *reinterpret_cast<__half2*>(row + lane * 4 + 2) = b;
    a.x = __float2half_rn(v1.x * inv); a.y = __float2half_rn(v1.y * inv);
    b.x = __float2half_rn(v1.z * inv); b.y = __float2half_rn(v1.w * inv);
    *reinterpret_cast<__half2*>(row + (lane + 32) * 4) = a;
    *reinterpret_cast<__half2*>(row + (lane + 32) * 4 + 2) = b;
}

// ---------------- HMMA fp16 GEMM (pre-normalized operands) ----------------
// 128x256 tile, 16 warps in 2(M) x 8(N), warp tile 64x32, K=256 in 4 chunks.
__global__ __launch_bounds__(NTHREADS, 1)
void cosine_hmma_kernel(const __half* __restrict__ Xs,
                        const __half* __restrict__ Ps,
                        float* __restrict__ out) {
    extern __shared__ __align__(1024) char smem[];
    const uint32_t sb = smem_u32(smem);
    const int tid = threadIdx.x;
    const int wid = tid >> 5;
    const int lane = tid & 31;
    const int m0 = blockIdx.y * BM;
    const int n0 = blockIdx.x * BN;

    const int wm = (wid & 1) * 64;     // 0 / 64
    const int wn = (wid >> 1) * 32;    // 0..224

    uint32_t aBase[4], bBase[4], aSel[4], bSel[4];
#pragma unroll
    for (int im = 0; im < 4; im++) {
        int rA = wm + im * 16 + (lane & 15);
        aBase[im] = rA * 128;
        aSel[im] = rA & 7;
    }
#pragma unroll
    for (int in = 0; in < 4; in++) {
        int rB = wn + in * 8 + (lane & 7);
        bBase[in] = 16384 + rB * 128;
        bSel[in] = rB & 7;
    }
    const uint32_t hiA = lane >> 4;
    const uint32_t hiB = (lane >> 3) & 1;

    float acc[4][4][4];
#pragma unroll
    for (int im = 0; im < 4; im++)
#pragma unroll
        for (int in = 0; in < 4; in++)
#pragma unroll
            for (int q = 0; q < 4; q++) acc[im][in][q] = 0.f;

    auto load_chunk = [&](int c, int s) {
        const int kOff = c * BK;
        const uint32_t aA = sb + s * STAGE_BYTES;
        const uint32_t bA = aA + 16384;
        // A: 128 rows x 8 chunks of 16B = 1024 units, 2 per thread
#pragma unroll
        for (int i = 0; i < 2; i++) {
            int u = tid + i * NTHREADS;
            int row = u >> 3, ch = u & 7;
            const char* g = (const char*)(Xs + (size_t)(m0 + row) * D_DIM + kOff) + ch * 16;
            cp_async16(aA + sw128(row * 128 + ch * 16), g, 16);
        }
        // B: 256 rows x 8 chunks = 2048 units, 4 per thread
#pragma unroll
        for (int i = 0; i < 4; i++) {
            int u = tid + i * NTHREADS;
            int row = u >> 3, ch = u & 7;
            int pr = n0 + row;
            uint32_t ok = (pr < C_ROWS) ? 16u : 0u;
            const char* g = (const char*)(Ps + (size_t)(ok ? pr : 0) * D_DIM + kOff) + ch * 16;
            cp_async16(bA + sw128(row * 128 + ch * 16), g, ok);
        }
        CP_COMMIT();
    };

    load_chunk(0, 0);
    load_chunk(1, 1);

    for (int c = 0; c < NCHUNK; c++) {
        const int s = c % STAGES;
        if (c == NCHUNK - 1) cp_wait<0>(); else cp_wait<1>();
        __syncthreads();   // stage c ready; all warps done with chunk c-1

        if (c + 2 < NCHUNK) load_chunk(c + 2, (c + 2) % STAGES);

        const uint32_t base = sb + s * STAGE_BYTES;
#pragma unroll
        for (int kk = 0; kk < 4; kk++) {
            uint32_t aF[4][4], bF[4][2];
#pragma unroll
            for (int im = 0; im < 4; im++)
                ldsm_x4(aF[im], base + aBase[im] + ((((kk * 2 + hiA) ^ aSel[im])) << 4));
#pragma unroll
            for (int in = 0; in < 4; in++)
                ldsm_x2(bF[in], base + bBase[in] + ((((kk * 2 + hiB) ^ bSel[in])) << 4));
#pragma unroll
            for (int im = 0; im < 4; im++)
#pragma unroll
                for (int in = 0; in < 4; in++)
                    mma_fp16(acc[im][in], aF[im], bF[in]);
        }
    }

    // ---- epilogue: plain stores (operands pre-normalized -> acc is cosine) ----
    const int mrow0 = m0 + wm + (lane >> 2);
    const int ncol0 = n0 + wn + (lane & 3) * 2;
#pragma unroll
    for (int im = 0; im < 4; im++) {
        const int mA = mrow0 + im * 16;
        float* orow0 = out + (size_t)mA * C_ROWS;
        float* orow1 = out + (size_t)(mA + 8) * C_ROWS;
#pragma unroll
        for (int in = 0; in < 4; in++) {
            const int n = ncol0 + in * 8;
            if (n < C_ROWS) {
                float2 v0, v1;
                v0.x = acc[im][in][0]; v0.y = acc[im][in][1];
                v1.x = acc[im][in][2]; v1.y = acc[im][in][3];
                *reinterpret_cast<float2*>(orow0 + n) = v0;
                *reinterpret_cast<float2*>(orow1 + n) = v1;
            }
        }
    }
}

// ---------------- launch ----------------
extern "C" void kernel_launch(void* const* d_in, const int* in_sizes, int n_in,
                              void* d_out, int out_size) {
    const float* x = (const float*)d_in[0];         // [16384, 256]
    const float* protos = (const float*)d_in[1];    // [10000, 256]
    float* out = (float*)d_out;                     // [16384, 10000]

    __half *Xs, *Ps;
    cudaGetSymbolAddress((void**)&Xs, g_Xs);
    cudaGetSymbolAddress((void**)&Ps, g_Ps);

    normalize_fp16_kernel<<<(N_ROWS * 32 + 255) / 256, 256>>>(x, Xs, N_ROWS);
    normalize_fp16_kernel<<<(C_ROWS * 32 + 255) / 256, 256>>>(protos, Ps, C_ROWS);

    cudaFuncSetAttribute(cosine_hmma_kernel,
                         cudaFuncAttributeMaxDynamicSharedMemorySize, SMEM_TOTAL);
    dim3 grid((C_ROWS + BN - 1) / BN, N_ROWS / BM);   // (40, 128)
    cosine_hmma_kernel<<<grid, NTHREADS, SMEM_TOTAL>>>(Xs, Ps, out);
}

// round 9
// speedup vs baseline: 1.1582x; 1.1582x over previous
#include <cuda_runtime.h>
#include <cuda_fp16.h>
#include <cstdint>
#include <math.h>

#define N_ROWS 16384
#define C_ROWS 10000
#define D_DIM  256
#define EPS    1e-6f

#define BM 128
#define BN 128
#define BK 64               // K elements per compute chunk (128B rows)
#define NCHUNK 4            // K=256 / 64
#define STAGES 3
#define STAGE_BYTES 32768   // 16KB A + 16KB B
#define SMEM_TOTAL (STAGES * STAGE_BYTES)

// ---------------- device scratch (allocation-free rule) ----------------
__device__ __half g_Xs[(size_t)N_ROWS * D_DIM];   // normalized x, fp16
__device__ __half g_Ps[(size_t)C_ROWS * D_DIM];   // normalized p, fp16

// ---------------- helpers ----------------
__device__ __forceinline__ uint32_t smem_u32(const void* p) {
    uint32_t a;
    asm("{ .reg .u64 t; cvta.to.shared.u64 t, %1; cvt.u32.u64 %0, t; }" : "=r"(a) : "l"(p));
    return a;
}
__device__ __forceinline__ void cp_async16(uint32_t dst, const void* src, uint32_t src_bytes) {
    asm volatile("cp.async.cg.shared.global [%0], [%1], 16, %2;"
                 :: "r"(dst), "l"(src), "r"(src_bytes) : "memory");
}
#define CP_COMMIT() asm volatile("cp.async.commit_group;" ::: "memory")
template <int N>
__device__ __forceinline__ void cp_wait() {
    asm volatile("cp.async.wait_group %0;" :: "n"(N) : "memory");
}
__device__ __forceinline__ uint32_t sw128(uint32_t off) { return off ^ ((off >> 3) & 0x70); }

__device__ __forceinline__ void ldsm_x4(uint32_t* r, uint32_t addr) {
    asm volatile("ldmatrix.sync.aligned.m8n8.x4.shared.b16 {%0,%1,%2,%3}, [%4];"
                 : "=r"(r[0]), "=r"(r[1]), "=r"(r[2]), "=r"(r[3]) : "r"(addr));
}
__device__ __forceinline__ void ldsm_x2(uint32_t* r, uint32_t addr) {
    asm volatile("ldmatrix.sync.aligned.m8n8.x2.shared.b16 {%0,%1}, [%2];"
                 : "=r"(r[0]), "=r"(r[1]) : "r"(addr));
}
__device__ __forceinline__ void mma_fp16(float* d, const uint32_t* a, const uint32_t* b) {
    asm volatile("mma.sync.aligned.m16n8k16.row.col.f32.f16.f16.f32 "
                 "{%0,%1,%2,%3}, {%4,%5,%6,%7}, {%8,%9}, {%0,%1,%2,%3};"
                 : "+f"(d[0]), "+f"(d[1]), "+f"(d[2]), "+f"(d[3])
                 : "r"(a[0]), "r"(a[1]), "r"(a[2]), "r"(a[3]), "r"(b[0]), "r"(b[1]));
}

// ---------------- fused normalize + fp16 convert for BOTH arrays ----------------
// Warps [0, N_ROWS) handle x; warps [N_ROWS, N_ROWS + C_ROWS) handle prototypes.
__global__ void normalize_fp16_both(const float* __restrict__ x,
                                    const float* __restrict__ protos,
                                    __half* __restrict__ Xs,
                                    __half* __restrict__ Ps) {
    int warp = (blockIdx.x * blockDim.x + threadIdx.x) >> 5;
    int lane = threadIdx.x & 31;
    const float* src;
    __half* dst;
    if (warp < N_ROWS) {
        src = x + (size_t)warp * D_DIM;
        dst = Xs + (size_t)warp * D_DIM;
    } else {
        int r = warp - N_ROWS;
        if (r >= C_ROWS) return;
        src = protos + (size_t)r * D_DIM;
        dst = Ps + (size_t)r * D_DIM;
    }
    const float4* p = reinterpret_cast<const float4*>(src);
    float4 v0 = p[lane];
    float4 v1 = p[lane + 32];
    float sum = v0.x * v0.x + v0.y * v0.y + v0.z * v0.z + v0.w * v0.w
              + v1.x * v1.x + v1.y * v1.y + v1.z * v1.z + v1.w * v1.w;
#pragma unroll
    for (int o = 16; o > 0; o >>= 1) sum += __shfl_xor_sync(0xffffffffu, sum, o);
    const float inv = 1.0f / fmaxf(sqrtf(sum), EPS);

    __half2 a, b;
    a.x = __float2half_rn(v0.x * inv); a.y = __float2half_rn(v0.y * inv);
    b.x = __float2half_rn(v0.z * inv); b.y = __float2half_rn(v0.w * inv);
    *reinterpret_cast<__half2*>(dst + lane * 4) = a;
    *reinterpret_cast<__half2*>(dst + lane * 4 + 2) = b;
    a.x = __float2half_rn(v1.x * inv); a.y = __float2half_rn(v1.y * inv);
    b.x = __float2half_rn(v1.z * inv); b.y = __float2half_rn(v1.w * inv);
    *reinterpret_cast<__half2*>(dst + (lane + 32) * 4) = a;
    *reinterpret_cast<__half2*>(dst + (lane + 32) * 4 + 2) = b;
}

// ---------------- HMMA fp16 GEMM (pre-normalized operands) ----------------
// 128x128 tile, 8 warps in 2(M) x 4(N), warp tile 64x32, K=256 in 4 chunks.
__global__ __launch_bounds__(256, 2)
void cosine_hmma_kernel(const __half* __restrict__ Xs,
                        const __half* __restrict__ Ps,
                        float* __restrict__ out) {
    extern __shared__ __align__(1024) char smem[];
    const uint32_t sb = smem_u32(smem);
    const int tid = threadIdx.x;
    const int wid = tid >> 5;
    const int lane = tid & 31;
    const int m0 = blockIdx.y * BM;
    const int n0 = blockIdx.x * BN;

    const int wm = (wid & 1) * 64;
    const int wn = (wid >> 1) * 32;

    uint32_t aBase[4], bBase[4], aSel[4], bSel[4];
#pragma unroll
    for (int im = 0; im < 4; im++) {
        int rA = wm + im * 16 + (lane & 15);
        aBase[im] = rA * 128;
        aSel[im] = rA & 7;
    }
#pragma unroll
    for (int in = 0; in < 4; in++) {
        int rB = wn + in * 8 + (lane & 7);
        bBase[in] = 16384 + rB * 128;
        bSel[in] = rB & 7;
    }
    const uint32_t hiA = lane >> 4;
    const uint32_t hiB = (lane >> 3) & 1;

    float acc[4][4][4];
#pragma unroll
    for (int im = 0; im < 4; im++)
#pragma unroll
        for (int in = 0; in < 4; in++)
#pragma unroll
            for (int q = 0; q < 4; q++) acc[im][in][q] = 0.f;

    auto load_chunk = [&](int c, int s) {
        const int kOff = c * BK;
        const uint32_t aA = sb + s * STAGE_BYTES;
        const uint32_t bA = aA + 16384;
#pragma unroll
        for (int i = 0; i < 4; i++) {
            int u = tid + i * 256;
            int row = u >> 3, ch = u & 7;
            const char* g = (const char*)(Xs + (size_t)(m0 + row) * D_DIM + kOff) + ch * 16;
            cp_async16(aA + sw128(row * 128 + ch * 16), g, 16);
        }
#pragma unroll
        for (int i = 0; i < 4; i++) {
            int u = tid + i * 256;
            int row = u >> 3, ch = u & 7;
            int pr = n0 + row;
            uint32_t ok = (pr < C_ROWS) ? 16u : 0u;
            const char* g = (const char*)(Ps + (size_t)(ok ? pr : 0) * D_DIM + kOff) + ch * 16;
            cp_async16(bA + sw128(row * 128 + ch * 16), g, ok);
        }
        CP_COMMIT();
    };

    load_chunk(0, 0);
    load_chunk(1, 1);

    for (int c = 0; c < NCHUNK; c++) {
        const int s = c % STAGES;
        if (c == NCHUNK - 1) cp_wait<0>(); else cp_wait<1>();
        __syncthreads();   // stage c ready; all warps done with chunk c-1

        if (c + 2 < NCHUNK) load_chunk(c + 2, (c + 2) % STAGES);

        const uint32_t base = sb + s * STAGE_BYTES;
#pragma unroll
        for (int kk = 0; kk < 4; kk++) {
            uint32_t aF[4][4], bF[4][2];
#pragma unroll
            for (int im = 0; im < 4; im++)
                ldsm_x4(aF[im], base + aBase[im] + ((((kk * 2 + hiA) ^ aSel[im])) << 4));
#pragma unroll
            for (int in = 0; in < 4; in++)
                ldsm_x2(bF[in], base + bBase[in] + ((((kk * 2 + hiB) ^ bSel[in])) << 4));
#pragma unroll
            for (int im = 0; im < 4; im++)
#pragma unroll
                for (int in = 0; in < 4; in++)
                    mma_fp16(acc[im][in], aF[im], bF[in]);
        }
    }

    // ---- epilogue: plain stores (operands pre-normalized -> acc is cosine) ----
    const int mrow0 = m0 + wm + (lane >> 2);
    const int ncol0 = n0 + wn + (lane & 3) * 2;
#pragma unroll
    for (int im = 0; im < 4; im++) {
        const int mA = mrow0 + im * 16;
        float* orow0 = out + (size_t)mA * C_ROWS;
        float* orow1 = out + (size_t)(mA + 8) * C_ROWS;
#pragma unroll
        for (int in = 0; in < 4; in++) {
            const int n = ncol0 + in * 8;
            if (n < C_ROWS) {
                float2 v0, v1;
                v0.x = acc[im][in][0]; v0.y = acc[im][in][1];
                v1.x = acc[im][in][2]; v1.y = acc[im][in][3];
                *reinterpret_cast<float2*>(orow0 + n) = v0;
                *reinterpret_cast<float2*>(orow1 + n) = v1;
            }
        }
    }
}

// ---------------- launch ----------------
extern "C" void kernel_launch(void* const* d_in, const int* in_sizes, int n_in,
                              void* d_out, int out_size) {
    const float* x = (const float*)d_in[0];         // [16384, 256]
    const float* protos = (const float*)d_in[1];    // [10000, 256]
    float* out = (float*)d_out;                     // [16384, 10000]

    __half *Xs, *Ps;
    cudaGetSymbolAddress((void**)&Xs, g_Xs);
    cudaGetSymbolAddress((void**)&Ps, g_Ps);

    // One launch normalizes both arrays: (16384 + 10000) warps.
    int total_warps = N_ROWS + C_ROWS;
    normalize_fp16_both<<<(total_warps * 32 + 255) / 256, 256>>>(x, protos, Xs, Ps);

    cudaFuncSetAttribute(cosine_hmma_kernel,
                         cudaFuncAttributeMaxDynamicSharedMemorySize, SMEM_TOTAL);
    dim3 grid((C_ROWS + BN - 1) / BN, N_ROWS / BM);   // (79, 128)
    cosine_hmma_kernel<<<grid, 256, SMEM_TOTAL>>>(Xs, Ps, out);
}

// round 10
// speedup vs baseline: 1.2333x; 1.0648x over previous
#include <cuda_runtime.h>
#include <cuda_fp16.h>
#include <cstdint>
#include <math.h>

#define N_ROWS 16384
#define C_ROWS 10000
#define D_DIM  256
#define EPS    1e-6f

#define BM 128
#define BN 128
#define BK 64               // K elements per compute chunk (128B rows)
#define NCHUNK 4            // K=256 / 64
#define STAGES 3
#define STAGE_BYTES 32768   // 16KB A + 16KB B
#define SMEM_TOTAL (STAGES * STAGE_BYTES)
#define NTHREADS 128        // 4 warps, each 64x64

// ---------------- device scratch (allocation-free rule) ----------------
__device__ __half g_Xs[(size_t)N_ROWS * D_DIM];   // normalized x, fp16
__device__ __half g_Ps[(size_t)C_ROWS * D_DIM];   // normalized p, fp16

// ---------------- helpers ----------------
__device__ __forceinline__ uint32_t smem_u32(const void* p) {
    uint32_t a;
    asm("{ .reg .u64 t; cvta.to.shared.u64 t, %1; cvt.u32.u64 %0, t; }" : "=r"(a) : "l"(p));
    return a;
}
__device__ __forceinline__ void cp_async16(uint32_t dst, const void* src, uint32_t src_bytes) {
    asm volatile("cp.async.cg.shared.global [%0], [%1], 16, %2;"
                 :: "r"(dst), "l"(src), "r"(src_bytes) : "memory");
}
#define CP_COMMIT() asm volatile("cp.async.commit_group;" ::: "memory")
template <int N>
__device__ __forceinline__ void cp_wait() {
    asm volatile("cp.async.wait_group %0;" :: "n"(N) : "memory");
}
__device__ __forceinline__ uint32_t sw128(uint32_t off) { return off ^ ((off >> 3) & 0x70); }

__device__ __forceinline__ void ldsm_x4(uint32_t* r, uint32_t addr) {
    asm volatile("ldmatrix.sync.aligned.m8n8.x4.shared.b16 {%0,%1,%2,%3}, [%4];"
                 : "=r"(r[0]), "=r"(r[1]), "=r"(r[2]), "=r"(r[3]) : "r"(addr));
}
__device__ __forceinline__ void mma_fp16(float* d, const uint32_t* a, const uint32_t* b) {
    asm volatile("mma.sync.aligned.m16n8k16.row.col.f32.f16.f16.f32 "
                 "{%0,%1,%2,%3}, {%4,%5,%6,%7}, {%8,%9}, {%0,%1,%2,%3};"
                 : "+f"(d[0]), "+f"(d[1]), "+f"(d[2]), "+f"(d[3])
                 : "r"(a[0]), "r"(a[1]), "r"(a[2]), "r"(a[3]), "r"(b[0]), "r"(b[1]));
}

// ---------------- fused normalize + fp16 convert for BOTH arrays ----------------
__global__ void normalize_fp16_both(const float* __restrict__ x,
                                    const float* __restrict__ protos,
                                    __half* __restrict__ Xs,
                                    __half* __restrict__ Ps) {
    int warp = (blockIdx.x * blockDim.x + threadIdx.x) >> 5;
    int lane = threadIdx.x & 31;
    const float* src;
    __half* dst;
    if (warp < N_ROWS) {
        src = x + (size_t)warp * D_DIM;
        dst = Xs + (size_t)warp * D_DIM;
    } else {
        int r = warp - N_ROWS;
        if (r >= C_ROWS) return;
        src = protos + (size_t)r * D_DIM;
        dst = Ps + (size_t)r * D_DIM;
    }
    const float4* p = reinterpret_cast<const float4*>(src);
    float4 v0 = p[lane];
    float4 v1 = p[lane + 32];
    float sum = v0.x * v0.x + v0.y * v0.y + v0.z * v0.z + v0.w * v0.w
              + v1.x * v1.x + v1.y * v1.y + v1.z * v1.z + v1.w * v1.w;
#pragma unroll
    for (int o = 16; o > 0; o >>= 1) sum += __shfl_xor_sync(0xffffffffu, sum, o);
    const float inv = 1.0f / fmaxf(sqrtf(sum), EPS);

    __half2 a, b;
    a.x = __float2half_rn(v0.x * inv); a.y = __float2half_rn(v0.y * inv);
    b.x = __float2half_rn(v0.z * inv); b.y = __float2half_rn(v0.w * inv);
    *reinterpret_cast<__half2*>(dst + lane * 4) = a;
    *reinterpret_cast<__half2*>(dst + lane * 4 + 2) = b;
    a.x = __float2half_rn(v1.x * inv); a.y = __float2half_rn(v1.y * inv);
    b.x = __float2half_rn(v1.z * inv); b.y = __float2half_rn(v1.w * inv);
    *reinterpret_cast<__half2*>(dst + (lane + 32) * 4) = a;
    *reinterpret_cast<__half2*>(dst + (lane + 32) * 4 + 2) = b;
}

// ---------------- HMMA fp16 GEMM (pre-normalized operands) ----------------
// 128x128 tile, 4 warps in 2(M) x 2(N), warp tile 64x64, K=256 in 4 chunks.
__global__ __launch_bounds__(NTHREADS, 2)
void cosine_hmma_kernel(const __half* __restrict__ Xs,
                        const __half* __restrict__ Ps,
                        float* __restrict__ out) {
    extern __shared__ __align__(1024) char smem[];
    const uint32_t sb = smem_u32(smem);
    const int tid = threadIdx.x;
    const int wid = tid >> 5;
    const int lane = tid & 31;
    const int m0 = blockIdx.y * BM;
    const int n0 = blockIdx.x * BN;

    const int wm = (wid & 1) * 64;     // 0 / 64
    const int wn = (wid >> 1) * 64;    // 0 / 64

    // A: 4 ldsm_x4 per kk, rows wm + im*16 + (lane&15), k-half = lane>>4
    uint32_t aBase[4], aSel[4];
#pragma unroll
    for (int im = 0; im < 4; im++) {
        int rA = wm + im * 16 + (lane & 15);
        aBase[im] = rA * 128;
        aSel[im] = rA & 7;
    }
    // B: 4 ldsm_x4 per kk, each covers n16 x k16.
    // lanes 0-7: n[0:8) k-lo | 8-15: n[0:8) k-hi | 16-23: n[8:16) k-lo | 24-31: n[8:16) k-hi
    uint32_t bBase[4], bSel[4];
#pragma unroll
    for (int in = 0; in < 4; in++) {
        int rB = wn + in * 16 + ((lane >> 4) << 3) + (lane & 7);
        bBase[in] = 16384 + rB * 128;
        bSel[in] = rB & 7;
    }
    const uint32_t hiA = lane >> 4;
    const uint32_t hiB = (lane >> 3) & 1;

    float acc[4][8][4];
#pragma unroll
    for (int im = 0; im < 4; im++)
#pragma unroll
        for (int j = 0; j < 8; j++)
#pragma unroll
            for (int q = 0; q < 4; q++) acc[im][j][q] = 0.f;

    auto load_chunk = [&](int c, int s) {
        const int kOff = c * BK;
        const uint32_t aA = sb + s * STAGE_BYTES;
        const uint32_t bA = aA + 16384;
        // A: 128 rows x 8 units of 16B = 1024 units, 8 per thread
#pragma unroll
        for (int i = 0; i < 8; i++) {
            int u = tid + i * NTHREADS;
            int row = u >> 3, ch = u & 7;
            const char* g = (const char*)(Xs + (size_t)(m0 + row) * D_DIM + kOff) + ch * 16;
            cp_async16(aA + sw128(row * 128 + ch * 16), g, 16);
        }
        // B: same shape, zero-fill past C_ROWS
#pragma unroll
        for (int i = 0; i < 8; i++) {
            int u = tid + i * NTHREADS;
            int row = u >> 3, ch = u & 7;
            int pr = n0 + row;
            uint32_t ok = (pr < C_ROWS) ? 16u : 0u;
            const char* g = (const char*)(Ps + (size_t)(ok ? pr : 0) * D_DIM + kOff) + ch * 16;
            cp_async16(bA + sw128(row * 128 + ch * 16), g, ok);
        }
        CP_COMMIT();
    };

    load_chunk(0, 0);
    load_chunk(1, 1);

    for (int c = 0; c < NCHUNK; c++) {
        const int s = c % STAGES;
        if (c == NCHUNK - 1) cp_wait<0>(); else cp_wait<1>();
        __syncthreads();   // stage c ready; all warps done with chunk c-1

        if (c + 2 < NCHUNK) load_chunk(c + 2, (c + 2) % STAGES);

        const uint32_t base = sb + s * STAGE_BYTES;
#pragma unroll
        for (int kk = 0; kk < 4; kk++) {
            uint32_t aF[4][4], bF[4][4];
#pragma unroll
            for (int im = 0; im < 4; im++)
                ldsm_x4(aF[im], base + aBase[im] + ((((kk * 2 + hiA) ^ aSel[im])) << 4));
#pragma unroll
            for (int in = 0; in < 4; in++)
                ldsm_x4(bF[in], base + bBase[in] + ((((kk * 2 + hiB) ^ bSel[in])) << 4));
#pragma unroll
            for (int im = 0; im < 4; im++)
#pragma unroll
                for (int j = 0; j < 8; j++)
                    mma_fp16(acc[im][j], aF[im], &bF[j >> 1][(j & 1) * 2]);
        }
    }

    // ---- epilogue: plain stores (operands pre-normalized -> acc is cosine) ----
    const int mrow0 = m0 + wm + (lane >> 2);
    const int ncol0 = n0 + wn + (lane & 3) * 2;
#pragma unroll
    for (int im = 0; im < 4; im++) {
        const int mA = mrow0 + im * 16;
        float* orow0 = out + (size_t)mA * C_ROWS;
        float* orow1 = out + (size_t)(mA + 8) * C_ROWS;
#pragma unroll
        for (int j = 0; j < 8; j++) {
            const int n = ncol0 + j * 8;
            if (n < C_ROWS) {
                float2 v0, v1;
                v0.x = acc[im][j][0]; v0.y = acc[im][j][1];
                v1.x = acc[im][j][2]; v1.y = acc[im][j][3];
                *reinterpret_cast<float2*>(orow0 + n) = v0;
                *reinterpret_cast<float2*>(orow1 + n) = v1;
            }
        }
    }
}

// ---------------- launch ----------------
extern "C" void kernel_launch(void* const* d_in, const int* in_sizes, int n_in,
                              void* d_out, int out_size) {
    const float* x = (const float*)d_in[0];         // [16384, 256]
    const float* protos = (const float*)d_in[1];    // [10000, 256]
    float* out = (float*)d_out;                     // [16384, 10000]

    __half *Xs, *Ps;
    cudaGetSymbolAddress((void**)&Xs, g_Xs);
    cudaGetSymbolAddress((void**)&Ps, g_Ps);

    int total_warps = N_ROWS + C_ROWS;
    normalize_fp16_both<<<(total_warps * 32 + 255) / 256, 256>>>(x, protos, Xs, Ps);

    cudaFuncSetAttribute(cosine_hmma_kernel,
                         cudaFuncAttributeMaxDynamicSharedMemorySize, SMEM_TOTAL);
    dim3 grid((C_ROWS + BN - 1) / BN, N_ROWS / BM);   // (79, 128)
    cosine_hmma_kernel<<<grid, NTHREADS, SMEM_TOTAL>>>(Xs, Ps, out);
}

// round 11
// speedup vs baseline: 1.2436x; 1.0083x over previous
#include <cuda_runtime.h>
#include <cuda_fp16.h>
#include <cstdint>
#include <math.h>

#define N_ROWS 16384
#define C_ROWS 10000
#define D_DIM  256
#define EPS    1e-6f

#define BM 128
#define BN 128
#define BK 64               // K elements per compute chunk (128B rows)
#define NCHUNK 4            // K=256 / 64
#define STAGES 3
#define STAGE_BYTES 32768   // 16KB A + 16KB B
#define SMEM_TOTAL (STAGES * STAGE_BYTES)
#define NTHREADS 128        // 4 warps, each 64x64

// ---------------- device scratch (allocation-free rule) ----------------
__device__ __half g_Xs[(size_t)N_ROWS * D_DIM];   // normalized x, fp16
__device__ __half g_Ps[(size_t)C_ROWS * D_DIM];   // normalized p, fp16

// ---------------- helpers ----------------
__device__ __forceinline__ uint32_t smem_u32(const void* p) {
    uint32_t a;
    asm("{ .reg .u64 t; cvta.to.shared.u64 t, %1; cvt.u32.u64 %0, t; }" : "=r"(a) : "l"(p));
    return a;
}
__device__ __forceinline__ void cp_async16(uint32_t dst, const void* src, uint32_t src_bytes) {
    asm volatile("cp.async.cg.shared.global [%0], [%1], 16, %2;"
                 :: "r"(dst), "l"(src), "r"(src_bytes) : "memory");
}
#define CP_COMMIT() asm volatile("cp.async.commit_group;" ::: "memory")
template <int N>
__device__ __forceinline__ void cp_wait() {
    asm volatile("cp.async.wait_group %0;" :: "n"(N) : "memory");
}
__device__ __forceinline__ uint32_t sw128(uint32_t off) { return off ^ ((off >> 3) & 0x70); }

__device__ __forceinline__ void ldsm_x4(uint32_t* r, uint32_t addr) {
    asm volatile("ldmatrix.sync.aligned.m8n8.x4.shared.b16 {%0,%1,%2,%3}, [%4];"
                 : "=r"(r[0]), "=r"(r[1]), "=r"(r[2]), "=r"(r[3]) : "r"(addr));
}
__device__ __forceinline__ void mma_fp16(float* d, const uint32_t* a, const uint32_t* b) {
    asm volatile("mma.sync.aligned.m16n8k16.row.col.f32.f16.f16.f32 "
                 "{%0,%1,%2,%3}, {%4,%5,%6,%7}, {%8,%9}, {%0,%1,%2,%3};"
                 : "+f"(d[0]), "+f"(d[1]), "+f"(d[2]), "+f"(d[3])
                 : "r"(a[0]), "r"(a[1]), "r"(a[2]), "r"(a[3]), "r"(b[0]), "r"(b[1]));
}
__device__ __forceinline__ void stg_cs_v2(float* p, float x, float y) {
    asm volatile("st.global.cs.v2.f32 [%0], {%1, %2};" :: "l"(p), "f"(x), "f"(y) : "memory");
}

// ---------------- fused normalize + fp16 convert for BOTH arrays ----------------
__global__ void normalize_fp16_both(const float* __restrict__ x,
                                    const float* __restrict__ protos,
                                    __half* __restrict__ Xs,
                                    __half* __restrict__ Ps) {
    int warp = (blockIdx.x * blockDim.x + threadIdx.x) >> 5;
    int lane = threadIdx.x & 31;
    const float* src;
    __half* dst;
    if (warp < N_ROWS) {
        src = x + (size_t)warp * D_DIM;
        dst = Xs + (size_t)warp * D_DIM;
    } else {
        int r = warp - N_ROWS;
        if (r >= C_ROWS) return;
        src = protos + (size_t)r * D_DIM;
        dst = Ps + (size_t)r * D_DIM;
    }
    const float4* p = reinterpret_cast<const float4*>(src);
    float4 v0 = p[lane];
    float4 v1 = p[lane + 32];
    float sum = v0.x * v0.x + v0.y * v0.y + v0.z * v0.z + v0.w * v0.w
              + v1.x * v1.x + v1.y * v1.y + v1.z * v1.z + v1.w * v1.w;
#pragma unroll
    for (int o = 16; o > 0; o >>= 1) sum += __shfl_xor_sync(0xffffffffu, sum, o);
    const float inv = 1.0f / fmaxf(sqrtf(sum), EPS);

    __half2 a, b;
    a.x = __float2half_rn(v0.x * inv); a.y = __float2half_rn(v0.y * inv);
    b.x = __float2half_rn(v0.z * inv); b.y = __float2half_rn(v0.w * inv);
    *reinterpret_cast<__half2*>(dst + lane * 4) = a;
    *reinterpret_cast<__half2*>(dst + lane * 4 + 2) = b;
    a.x = __float2half_rn(v1.x * inv); a.y = __float2half_rn(v1.y * inv);
    b.x = __float2half_rn(v1.z * inv); b.y = __float2half_rn(v1.w * inv);
    *reinterpret_cast<__half2*>(dst + (lane + 32) * 4) = a;
    *reinterpret_cast<__half2*>(dst + (lane + 32) * 4 + 2) = b;
}

// ---------------- HMMA fp16 GEMM (pre-normalized operands) ----------------
// 128x128 tile, 4 warps in 2(M) x 2(N), warp tile 64x64, K=256 in 4 chunks.
__global__ __launch_bounds__(NTHREADS, 2)
void cosine_hmma_kernel(const __half* __restrict__ Xs,
                        const __half* __restrict__ Ps,
                        float* __restrict__ out) {
    extern __shared__ __align__(1024) char smem[];
    const uint32_t sb = smem_u32(smem);
    const int tid = threadIdx.x;
    const int wid = tid >> 5;
    const int lane = tid & 31;
    const int m0 = blockIdx.y * BM;
    const int n0 = blockIdx.x * BN;

    const int wm = (wid & 1) * 64;     // 0 / 64
    const int wn = (wid >> 1) * 64;    // 0 / 64

    uint32_t aBase[4], aSel[4];
#pragma unroll
    for (int im = 0; im < 4; im++) {
        int rA = wm + im * 16 + (lane & 15);
        aBase[im] = rA * 128;
        aSel[im] = rA & 7;
    }
    uint32_t bBase[4], bSel[4];
#pragma unroll
    for (int in = 0; in < 4; in++) {
        int rB = wn + in * 16 + ((lane >> 4) << 3) + (lane & 7);
        bBase[in] = 16384 + rB * 128;
        bSel[in] = rB & 7;
    }
    const uint32_t hiA = lane >> 4;
    const uint32_t hiB = (lane >> 3) & 1;

    float acc[4][8][4];
#pragma unroll
    for (int im = 0; im < 4; im++)
#pragma unroll
        for (int j = 0; j < 8; j++)
#pragma unroll
            for (int q = 0; q < 4; q++) acc[im][j][q] = 0.f;

    auto load_chunk = [&](int c, int s) {
        const int kOff = c * BK;
        const uint32_t aA = sb + s * STAGE_BYTES;
        const uint32_t bA = aA + 16384;
#pragma unroll
        for (int i = 0; i < 8; i++) {
            int u = tid + i * NTHREADS;
            int row = u >> 3, ch = u & 7;
            const char* g = (const char*)(Xs + (size_t)(m0 + row) * D_DIM + kOff) + ch * 16;
            cp_async16(aA + sw128(row * 128 + ch * 16), g, 16);
        }
#pragma unroll
        for (int i = 0; i < 8; i++) {
            int u = tid + i * NTHREADS;
            int row = u >> 3, ch = u & 7;
            int pr = n0 + row;
            uint32_t ok = (pr < C_ROWS) ? 16u : 0u;
            const char* g = (const char*)(Ps + (size_t)(ok ? pr : 0) * D_DIM + kOff) + ch * 16;
            cp_async16(bA + sw128(row * 128 + ch * 16), g, ok);
        }
        CP_COMMIT();
    };

    // One kk step: B frags first, A frags interleaved with MMA blocks.
    auto do_kk = [&](uint32_t base, int kk) {
        uint32_t aF[2][4], bF[4][4];
#pragma unroll
        for (int in = 0; in < 4; in++)
            ldsm_x4(bF[in], base + bBase[in] + ((((kk * 2 + hiB) ^ bSel[in])) << 4));
        ldsm_x4(aF[0], base + aBase[0] + ((((kk * 2 + hiA) ^ aSel[0])) << 4));
#pragma unroll
        for (int im = 0; im < 4; im++) {
            if (im < 3)
                ldsm_x4(aF[(im + 1) & 1],
                        base + aBase[im + 1] + ((((kk * 2 + hiA) ^ aSel[im + 1])) << 4));
#pragma unroll
            for (int j = 0; j < 8; j++)
                mma_fp16(acc[im][j], aF[im & 1], &bF[j >> 1][(j & 1) * 2]);
        }
    };

    load_chunk(0, 0);
    load_chunk(1, 1);

    for (int c = 0; c < NCHUNK; c++) {
        const int s = c % STAGES;
        if (c == NCHUNK - 1) cp_wait<0>(); else cp_wait<1>();
        __syncthreads();   // stage c ready; all warps done with chunk c-1

        const uint32_t base = sb + s * STAGE_BYTES;
        // kk=0 frags issue first; the next chunk's cp.asyncs drain under kk=0 MMAs
        do_kk(base, 0);
        if (c + 2 < NCHUNK) load_chunk(c + 2, (c + 2) % STAGES);
#pragma unroll
        for (int kk = 1; kk < 4; kk++) do_kk(base, kk);
    }

    // ---- epilogue: streaming stores (acc is cosine directly) ----
    const int mrow0 = m0 + wm + (lane >> 2);
    const int ncol0 = n0 + wn + (lane & 3) * 2;
#pragma unroll
    for (int im = 0; im < 4; im++) {
        const int mA = mrow0 + im * 16;
        float* orow0 = out + (size_t)mA * C_ROWS;
        float* orow1 = out + (size_t)(mA + 8) * C_ROWS;
#pragma unroll
        for (int j = 0; j < 8; j++) {
            const int n = ncol0 + j * 8;
            if (n < C_ROWS) {
                stg_cs_v2(orow0 + n, acc[im][j][0], acc[im][j][1]);
                stg_cs_v2(orow1 + n, acc[im][j][2], acc[im][j][3]);
            }
        }
    }
}

// ---------------- launch ----------------
extern "C" void kernel_launch(void* const* d_in, const int* in_sizes, int n_in,
                              void* d_out, int out_size) {
    const float* x = (const float*)d_in[0];         // [16384, 256]
    const float* protos = (const float*)d_in[1];    // [10000, 256]
    float* out = (float*)d_out;                     // [16384, 10000]

    __half *Xs, *Ps;
    cudaGetSymbolAddress((void**)&Xs, g_Xs);
    cudaGetSymbolAddress((void**)&Ps, g_Ps);

    int total_warps = N_ROWS + C_ROWS;
    normalize_fp16_both<<<(total_warps * 32 + 255) / 256, 256>>>(x, protos, Xs, Ps);

    cudaFuncSetAttribute(cosine_hmma_kernel,
                         cudaFuncAttributeMaxDynamicSharedMemorySize, SMEM_TOTAL);
    dim3 grid((C_ROWS + BN - 1) / BN, N_ROWS / BM);   // (79, 128)
    cosine_hmma_kernel<<<grid, NTHREADS, SMEM_TOTAL>>>(Xs, Ps, out);
}